// round 3
// baseline (speedup 1.0000x reference)
#include <cuda_runtime.h>
#include <math.h>

// Problem constants
#define Bb   2
#define Ss   4096
#define Ee   768
#define Hh   12
#define Dd   64
#define Pp   16
#define LKV  4112            // Pp + Ss
#define BH   24              // Bb*Hh

typedef unsigned long long u64;

// ---- packed f32x2 helpers (Blackwell FFMA2 path; ptxas never emits these) ----
__device__ __forceinline__ u64 ffma2(u64 a, u64 b, u64 c) {
    u64 d;
    asm("fma.rn.f32x2 %0, %1, %2, %3;" : "=l"(d) : "l"(a), "l"(b), "l"(c));
    return d;
}
__device__ __forceinline__ u64 fmul2(u64 a, u64 b) {
    u64 d;
    asm("mul.rn.f32x2 %0, %1, %2;" : "=l"(d) : "l"(a), "l"(b));
    return d;
}
__device__ __forceinline__ u64 dup2(float x) {
    u64 d; unsigned r = __float_as_uint(x);
    asm("mov.b64 %0, {%1, %2};" : "=l"(d) : "r"(r), "r"(r));
    return d;
}
__device__ __forceinline__ u64 pack2(float lo, float hi) {
    u64 d; unsigned a = __float_as_uint(lo), b = __float_as_uint(hi);
    asm("mov.b64 %0, {%1, %2};" : "=l"(d) : "r"(a), "r"(b));
    return d;
}
__device__ __forceinline__ float2 unpack2(u64 v) {
    unsigned lo, hi;
    asm("mov.b64 {%0, %1}, %2;" : "=r"(lo), "=r"(hi) : "l"(v));
    return make_float2(__uint_as_float(lo), __uint_as_float(hi));
}

// Scratch (device globals: no allocation allowed)
__device__ float g_Q[(size_t)BH * Ss * Dd];     // [bh][s][d], pre-scaled by 1/8
__device__ float g_K[(size_t)BH * LKV * Dd];    // [bh][p+s][d]
__device__ float g_V[(size_t)BH * LKV * Dd];
__device__ float g_ctx[(size_t)Bb * Ss * Ee];   // [b][s][h*64+d]

// ---------------------------------------------------------------------------
// Prompt prefix scatter: prompt[B,2,P,H,D] -> g_K/g_V rows [bh][0..P)
// ---------------------------------------------------------------------------
__global__ void fill_prompt(const float* __restrict__ prompt) {
    int i = blockIdx.x * 256 + threadIdx.x;   // over Bb*Pp*Hh*Dd = 24576
    if (i >= Bb * Pp * Hh * Dd) return;
    int d = i & 63;
    int h = (i >> 6) % Hh;
    int p = (i >> 6) / Hh % Pp;
    int b = i / (64 * Hh * Pp);
    size_t src0 = ((((size_t)b * 2 + 0) * Pp + p) * Hh + h) * Dd + d;
    size_t src1 = ((((size_t)b * 2 + 1) * Pp + p) * Hh + h) * Dd + d;
    size_t dst  = (((size_t)(b * Hh + h)) * LKV + p) * Dd + d;
    g_K[dst] = prompt[src0];
    g_V[dst] = prompt[src1];
}

// ---------------------------------------------------------------------------
// NT SGEMM core: C[128,128] tile of A[M,768] @ W[N,768]^T + bias
// 256 threads, 8x8 micro-tile (rows packed pairwise into f32x2), transposed smem.
// mode 1: g_Q[bh][s][d]=0.125f*v  mode 2: g_K[..][Pp+s][d]=v
// mode 3: g_V[..][Pp+s][d]=v      mode 0: out[m*768+n]=v
// ---------------------------------------------------------------------------
__device__ __forceinline__
void sgemm_tile(const float* __restrict__ Arow, const float* __restrict__ Brow,
                const float* __restrict__ bias, float* __restrict__ out,
                int m0, int n0, int mode)
{
    __shared__ float As[16][132];   // [k][m]
    __shared__ float Bs[16][132];   // [k][n]

    const int tid = threadIdx.x;
    const int tx = tid & 15, ty = tid >> 4;

    u64 acc2[4][8];                 // rows packed: acc2[ip][j] = (row 2ip, row 2ip+1)
#pragma unroll
    for (int ip = 0; ip < 4; ip++)
#pragma unroll
        for (int j = 0; j < 8; j++) acc2[ip][j] = 0ull;   // two packed 0.0f

    for (int k0 = 0; k0 < Ee; k0 += 16) {
#pragma unroll
        for (int it = 0; it < 2; it++) {
            int v  = it * 256 + tid;
            int r  = v >> 2;
            int kq = (v & 3) << 2;
            float4 ta = *(const float4*)(Arow + (size_t)r * Ee + k0 + kq);
            As[kq + 0][r] = ta.x; As[kq + 1][r] = ta.y;
            As[kq + 2][r] = ta.z; As[kq + 3][r] = ta.w;
            float4 tb = *(const float4*)(Brow + (size_t)r * Ee + k0 + kq);
            Bs[kq + 0][r] = tb.x; Bs[kq + 1][r] = tb.y;
            Bs[kq + 2][r] = tb.z; Bs[kq + 3][r] = tb.w;
        }
        __syncthreads();

#pragma unroll
        for (int kk = 0; kk < 16; kk++) {
            // a rows: two LDS.128, register pairs ARE the packed f32x2 operands
            ulonglong2 av0 = *(const ulonglong2*)&As[kk][ty * 8];
            ulonglong2 av1 = *(const ulonglong2*)&As[kk][ty * 8 + 4];
            u64 a2[4] = { av0.x, av0.y, av1.x, av1.y };
            float4 b0 = *(const float4*)&Bs[kk][tx * 8];
            float4 b1 = *(const float4*)&Bs[kk][tx * 8 + 4];
            u64 bd[8] = { dup2(b0.x), dup2(b0.y), dup2(b0.z), dup2(b0.w),
                          dup2(b1.x), dup2(b1.y), dup2(b1.z), dup2(b1.w) };
#pragma unroll
            for (int ip = 0; ip < 4; ip++)
#pragma unroll
                for (int j = 0; j < 8; j++)
                    acc2[ip][j] = ffma2(a2[ip], bd[j], acc2[ip][j]);
        }
        __syncthreads();
    }

    // Epilogue (bias hoisted)
    float bb[8];
#pragma unroll
    for (int j = 0; j < 8; j++) bb[j] = bias[n0 + tx * 8 + j];

#pragma unroll
    for (int ip = 0; ip < 4; ip++) {
#pragma unroll
        for (int j = 0; j < 8; j++) {
            float2 v2 = unpack2(acc2[ip][j]);
            int n = n0 + tx * 8 + j;
            float vr[2] = { v2.x + bb[j], v2.y + bb[j] };
#pragma unroll
            for (int hlf = 0; hlf < 2; hlf++) {
                int m = m0 + ty * 8 + ip * 2 + hlf;
                float v = vr[hlf];
                if (mode == 0) {
                    out[(size_t)m * Ee + n] = v;
                } else {
                    int b = m >> 12, s = m & 4095;   // Ss = 4096
                    int h = n >> 6,  d = n & 63;
                    int bh = b * Hh + h;
                    if (mode == 1) {
                        g_Q[(((size_t)bh) * Ss + s) * Dd + d] = 0.125f * v;
                    } else if (mode == 2) {
                        g_K[(((size_t)bh) * LKV + Pp + s) * Dd + d] = v;
                    } else {
                        g_V[(((size_t)bh) * LKV + Pp + s) * Dd + d] = v;
                    }
                }
            }
        }
    }
}

// Fused QKV projections: blockIdx.z in {0,1,2} -> Q,K,V
__global__ __launch_bounds__(256, 2)
void sgemm_qkv(const float* __restrict__ query, const float* __restrict__ key,
               const float* __restrict__ value,
               const float* __restrict__ Wq, const float* __restrict__ bq,
               const float* __restrict__ Wk, const float* __restrict__ bk,
               const float* __restrict__ Wv, const float* __restrict__ bv)
{
    const int m0 = blockIdx.y * 128, n0 = blockIdx.x * 128;
    const int z = blockIdx.z;
    const float* A = (z == 0) ? query : (z == 1) ? key : value;
    const float* W = (z == 0) ? Wq : (z == 1) ? Wk : Wv;
    const float* bi = (z == 0) ? bq : (z == 1) ? bk : bv;
    sgemm_tile(A + (size_t)m0 * Ee, W + (size_t)n0 * Ee, bi, nullptr,
               m0, n0, z + 1);
}

// Final output projection: out = g_ctx @ Wo^T + bo
__global__ __launch_bounds__(256, 2)
void sgemm_out(const float* __restrict__ Wo, const float* __restrict__ bo,
               float* __restrict__ out)
{
    const int m0 = blockIdx.y * 128, n0 = blockIdx.x * 128;
    sgemm_tile(g_ctx + (size_t)m0 * Ee, Wo + (size_t)n0 * Ee, bo, out,
               m0, n0, 0);
}

// ---------------------------------------------------------------------------
// Flash attention, fp32 with packed-f32x2 MMA cores.
// One block = (b, h, 128-query tile). BQ=128, BKV=64, D=64; 256 threads;
// thread (ty,tx): 8 q-rows (4 f32x2 pairs) x 4 cols.
// Smem: Qs[d][q] 64x132, Ks[d][kv] 64x68, Vs[kv][d] 64x68, Ps[kv][q] 64x132
//  -> 102400 bytes dynamic.
// ---------------------------------------------------------------------------
#define QS(d_, q_) Qs[(d_) * 132 + (q_)]
#define KS(d_, k_) Ks[(d_) * 68 + (k_)]
#define VS(k_, d_) Vs[(k_) * 68 + (d_)]
#define PS(k_, q_) Ps[(k_) * 132 + (q_)]

__global__ __launch_bounds__(256, 2)
void attn_kernel()
{
    extern __shared__ float sm[];
    float* Qs = sm;                    // 64*132 = 8448
    float* Ks = Qs + 64 * 132;         // 64*68  = 4352
    float* Vs = Ks + 64 * 68;          // 64*68  = 4352
    float* Ps = Vs + 64 * 68;          // 64*132 = 8448   total 25600 floats

    const int tid = threadIdx.x;
    const int tx = tid & 15, ty = tid >> 4;
    const int qt = blockIdx.x, h = blockIdx.y, b = blockIdx.z;
    const int bh = b * Hh + h;

    const float* Qg = g_Q + (((size_t)bh) * Ss + (size_t)qt * 128) * Dd;
    const float* Kg = g_K + ((size_t)bh) * LKV * Dd;
    const float* Vg = g_V + ((size_t)bh) * LKV * Dd;

    // Load Q tile (128 x 64), transposed into Qs[d][q]
#pragma unroll
    for (int it = 0; it < 8; it++) {
        int v  = it * 256 + tid;
        int q  = v >> 4;
        int d4 = (v & 15) << 2;
        float4 t = *(const float4*)(Qg + (size_t)q * Dd + d4);
        QS(d4 + 0, q) = t.x; QS(d4 + 1, q) = t.y;
        QS(d4 + 2, q) = t.z; QS(d4 + 3, q) = t.w;
    }

    float m_i[8], l_i[8];
    u64 o2[4][4];                      // rows packed pairwise
#pragma unroll
    for (int i = 0; i < 8; i++) { m_i[i] = -1e30f; l_i[i] = 0.f; }
#pragma unroll
    for (int ip = 0; ip < 4; ip++)
#pragma unroll
        for (int j = 0; j < 4; j++) o2[ip][j] = 0ull;

    const int NT = (LKV + 63) / 64;   // 65 tiles, last has 16 valid
    for (int t = 0; t < NT; t++) {
        const int kv0 = t * 64;
        __syncthreads();   // prev PV done before overwriting Ks/Vs

        // Load K (transposed) and V tiles; zero-fill out-of-range rows
#pragma unroll
        for (int it = 0; it < 4; it++) {
            int v  = it * 256 + tid;
            int kv = v >> 4;
            int d4 = (v & 15) << 2;
            float4 kd, vd;
            if (kv0 + kv < LKV) {
                kd = *(const float4*)(Kg + (size_t)(kv0 + kv) * Dd + d4);
                vd = *(const float4*)(Vg + (size_t)(kv0 + kv) * Dd + d4);
            } else {
                kd = make_float4(0.f, 0.f, 0.f, 0.f);
                vd = kd;
            }
            KS(d4 + 0, kv) = kd.x; KS(d4 + 1, kv) = kd.y;
            KS(d4 + 2, kv) = kd.z; KS(d4 + 3, kv) = kd.w;
            *(float4*)&VS(kv, d4) = vd;
        }
        __syncthreads();

        // S = Q @ K^T  (128 x 64, K-dim = 64), rows packed into f32x2
        u64 s2[4][4];
#pragma unroll
        for (int ip = 0; ip < 4; ip++)
#pragma unroll
            for (int j = 0; j < 4; j++) s2[ip][j] = 0ull;

#pragma unroll 16
        for (int k = 0; k < 64; k++) {
            ulonglong2 av0 = *(const ulonglong2*)&QS(k, ty * 8);
            ulonglong2 av1 = *(const ulonglong2*)&QS(k, ty * 8 + 4);
            u64 a2[4] = { av0.x, av0.y, av1.x, av1.y };
            float4 bv = *(const float4*)&KS(k, tx * 4);
            u64 bd[4] = { dup2(bv.x), dup2(bv.y), dup2(bv.z), dup2(bv.w) };
#pragma unroll
            for (int ip = 0; ip < 4; ip++)
#pragma unroll
                for (int j = 0; j < 4; j++)
                    s2[ip][j] = ffma2(a2[ip], bd[j], s2[ip][j]);
        }

        // Unpack scores
        float s[8][4];
#pragma unroll
        for (int ip = 0; ip < 4; ip++)
#pragma unroll
            for (int j = 0; j < 4; j++) {
                float2 v2 = unpack2(s2[ip][j]);
                s[ip * 2 + 0][j] = v2.x;
                s[ip * 2 + 1][j] = v2.y;
            }

        // Mask invalid keys (only last tile)
        if (kv0 + 64 > LKV) {
#pragma unroll
            for (int j = 0; j < 4; j++)
                if (kv0 + tx * 4 + j >= LKV)
#pragma unroll
                    for (int i = 0; i < 8; i++) s[i][j] = -1e30f;
        }

        // Online softmax (rows spread over the 16 tx-lanes sharing ty)
        float corr[8];
#pragma unroll
        for (int i = 0; i < 8; i++) {
            float mx = s[i][0];
#pragma unroll
            for (int j = 1; j < 4; j++) mx = fmaxf(mx, s[i][j]);
#pragma unroll
            for (int off = 8; off > 0; off >>= 1)
                mx = fmaxf(mx, __shfl_xor_sync(0xffffffffu, mx, off));
            float mn = fmaxf(m_i[i], mx);
            corr[i] = __expf(m_i[i] - mn);
            float sum = 0.f;
#pragma unroll
            for (int j = 0; j < 4; j++) {
                float e = __expf(s[i][j] - mn);
                s[i][j] = e;              // s now holds P
                sum += e;
            }
#pragma unroll
            for (int off = 8; off > 0; off >>= 1)
                sum += __shfl_xor_sync(0xffffffffu, sum, off);
            l_i[i] = l_i[i] * corr[i] + sum;
            m_i[i] = mn;
        }

        // Rescale packed O accumulator by per-row correction
#pragma unroll
        for (int ip = 0; ip < 4; ip++) {
            u64 c2 = pack2(corr[ip * 2], corr[ip * 2 + 1]);
#pragma unroll
            for (int j = 0; j < 4; j++) o2[ip][j] = fmul2(o2[ip][j], c2);
        }

        // Stage P (transposed) for the PV GEMM
#pragma unroll
        for (int j = 0; j < 4; j++) {
            int c = tx * 4 + j;
            *(float4*)&PS(c, ty * 8)     = make_float4(s[0][j], s[1][j], s[2][j], s[3][j]);
            *(float4*)&PS(c, ty * 8 + 4) = make_float4(s[4][j], s[5][j], s[6][j], s[7][j]);
        }
        __syncthreads();

        // O += P @ V  (128 x 64, K-dim = 64; masked P rows are 0)
#pragma unroll 16
        for (int k = 0; k < 64; k++) {
            ulonglong2 av0 = *(const ulonglong2*)&PS(k, ty * 8);
            ulonglong2 av1 = *(const ulonglong2*)&PS(k, ty * 8 + 4);
            u64 a2[4] = { av0.x, av0.y, av1.x, av1.y };
            float4 vv = *(const float4*)&VS(k, tx * 4);
            u64 bd[4] = { dup2(vv.x), dup2(vv.y), dup2(vv.z), dup2(vv.w) };
#pragma unroll
            for (int ip = 0; ip < 4; ip++)
#pragma unroll
                for (int j = 0; j < 4; j++)
                    o2[ip][j] = ffma2(a2[ip], bd[j], o2[ip][j]);
        }
    }

    // Epilogue: normalize and write ctx[b][q][h*64 + d]
    float* Cg = g_ctx + (((size_t)b * Ss) + (size_t)qt * 128) * Ee + h * Dd + tx * 4;
#pragma unroll
    for (int ip = 0; ip < 4; ip++) {
#pragma unroll
        for (int hlf = 0; hlf < 2; hlf++) {
            int i = ip * 2 + hlf;
            float inv = 1.f / l_i[i];
            int q = ty * 8 + i;
            float2 v0 = unpack2(o2[ip][0]);
            float2 v1 = unpack2(o2[ip][1]);
            float2 v2 = unpack2(o2[ip][2]);
            float2 v3 = unpack2(o2[ip][3]);
            float r0 = hlf ? v0.y : v0.x;
            float r1 = hlf ? v1.y : v1.x;
            float r2 = hlf ? v2.y : v2.x;
            float r3 = hlf ? v3.y : v3.x;
            *(float4*)(Cg + (size_t)q * Ee) =
                make_float4(r0 * inv, r1 * inv, r2 * inv, r3 * inv);
        }
    }
}

// ---------------------------------------------------------------------------
extern "C" void kernel_launch(void* const* d_in, const int* in_sizes, int n_in,
                              void* d_out, int out_size)
{
    const float* query  = (const float*)d_in[0];
    const float* key    = (const float*)d_in[1];
    const float* value  = (const float*)d_in[2];
    const float* prompt = (const float*)d_in[3];
    const float* Wq = (const float*)d_in[4];
    const float* bq = (const float*)d_in[5];
    const float* Wk = (const float*)d_in[6];
    const float* bk = (const float*)d_in[7];
    const float* Wv = (const float*)d_in[8];
    const float* bv = (const float*)d_in[9];
    const float* Wo = (const float*)d_in[10];
    const float* bo = (const float*)d_in[11];
    float* out = (float*)d_out;

    // Opt-in to >48KB dynamic smem for the attention kernel (idempotent, non-stream API)
    cudaFuncSetAttribute(attn_kernel, cudaFuncAttributeMaxDynamicSharedMemorySize, 102400);

    fill_prompt<<<(Bb * Pp * Hh * Dd + 255) / 256, 256>>>(prompt);

    dim3 gg(Ee / 128, (Bb * Ss) / 128, 3);   // (6, 64, 3) fused QKV
    sgemm_qkv<<<gg, 256>>>(query, key, value, Wq, bq, Wk, bk, Wv, bv);

    attn_kernel<<<dim3(Ss / 128, Hh, Bb), 256, 102400>>>();

    sgemm_out<<<dim3(Ee / 128, (Bb * Ss) / 128), 256>>>(Wo, bo, out);
}

// round 7
// speedup vs baseline: 1.4520x; 1.4520x over previous
#include <cuda_runtime.h>
#include <cuda_bf16.h>
#include <math.h>
#include <cstdint>

// Problem constants
#define Bb   2
#define Ss   4096
#define Ee   768
#define Hh   12
#define Dd   64
#define Pp   16
#define LKV  4112            // Pp + Ss
#define BH   24              // Bb*Hh

typedef unsigned long long u64;
typedef unsigned int u32;

// ---- packed f32x2 helpers (FFMA2) ----
__device__ __forceinline__ u64 ffma2(u64 a, u64 b, u64 c) {
    u64 d;
    asm("fma.rn.f32x2 %0, %1, %2, %3;" : "=l"(d) : "l"(a), "l"(b), "l"(c));
    return d;
}
__device__ __forceinline__ u64 dup2(float x) {
    u64 d; unsigned r = __float_as_uint(x);
    asm("mov.b64 %0, {%1, %2};" : "=l"(d) : "r"(r), "r"(r));
    return d;
}
__device__ __forceinline__ float2 unpack2(u64 v) {
    unsigned lo, hi;
    asm("mov.b64 {%0, %1}, %2;" : "=r"(lo), "=r"(hi) : "l"(v));
    return make_float2(__uint_as_float(lo), __uint_as_float(hi));
}

// Scratch (device globals: no allocation allowed)
__device__ float g_Q[(size_t)BH * Ss * Dd];     // [bh][s][d], pre-scaled by 1/8
__device__ float g_K[(size_t)BH * LKV * Dd];    // [bh][p+s][d]
__device__ float g_V[(size_t)BH * LKV * Dd];
__device__ float g_ctx[(size_t)Bb * Ss * Ee];   // [b][s][h*64+d]

// ---------------------------------------------------------------------------
// Prompt prefix scatter
// ---------------------------------------------------------------------------
__global__ void fill_prompt(const float* __restrict__ prompt) {
    int i = blockIdx.x * 256 + threadIdx.x;
    if (i >= Bb * Pp * Hh * Dd) return;
    int d = i & 63;
    int h = (i >> 6) % Hh;
    int p = (i >> 6) / Hh % Pp;
    int b = i / (64 * Hh * Pp);
    size_t src0 = ((((size_t)b * 2 + 0) * Pp + p) * Hh + h) * Dd + d;
    size_t src1 = ((((size_t)b * 2 + 1) * Pp + p) * Hh + h) * Dd + d;
    size_t dst  = (((size_t)(b * Hh + h)) * LKV + p) * Dd + d;
    g_K[dst] = prompt[src0];
    g_V[dst] = prompt[src1];
}

// ---------------------------------------------------------------------------
// NT SGEMM (FFMA2), unchanged from the passing R3 kernel
// ---------------------------------------------------------------------------
__device__ __forceinline__
void sgemm_tile(const float* __restrict__ Arow, const float* __restrict__ Brow,
                const float* __restrict__ bias, float* __restrict__ out,
                int m0, int n0, int mode)
{
    __shared__ float As[16][132];
    __shared__ float Bs[16][132];

    const int tid = threadIdx.x;
    const int tx = tid & 15, ty = tid >> 4;

    u64 acc2[4][8];
#pragma unroll
    for (int ip = 0; ip < 4; ip++)
#pragma unroll
        for (int j = 0; j < 8; j++) acc2[ip][j] = 0ull;

    for (int k0 = 0; k0 < Ee; k0 += 16) {
#pragma unroll
        for (int it = 0; it < 2; it++) {
            int v  = it * 256 + tid;
            int r  = v >> 2;
            int kq = (v & 3) << 2;
            float4 ta = *(const float4*)(Arow + (size_t)r * Ee + k0 + kq);
            As[kq + 0][r] = ta.x; As[kq + 1][r] = ta.y;
            As[kq + 2][r] = ta.z; As[kq + 3][r] = ta.w;
            float4 tb = *(const float4*)(Brow + (size_t)r * Ee + k0 + kq);
            Bs[kq + 0][r] = tb.x; Bs[kq + 1][r] = tb.y;
            Bs[kq + 2][r] = tb.z; Bs[kq + 3][r] = tb.w;
        }
        __syncthreads();

#pragma unroll
        for (int kk = 0; kk < 16; kk++) {
            ulonglong2 av0 = *(const ulonglong2*)&As[kk][ty * 8];
            ulonglong2 av1 = *(const ulonglong2*)&As[kk][ty * 8 + 4];
            u64 a2[4] = { av0.x, av0.y, av1.x, av1.y };
            float4 b0 = *(const float4*)&Bs[kk][tx * 8];
            float4 b1 = *(const float4*)&Bs[kk][tx * 8 + 4];
            u64 bd[8] = { dup2(b0.x), dup2(b0.y), dup2(b0.z), dup2(b0.w),
                          dup2(b1.x), dup2(b1.y), dup2(b1.z), dup2(b1.w) };
#pragma unroll
            for (int ip = 0; ip < 4; ip++)
#pragma unroll
                for (int j = 0; j < 8; j++)
                    acc2[ip][j] = ffma2(a2[ip], bd[j], acc2[ip][j]);
        }
        __syncthreads();
    }

    float bb[8];
#pragma unroll
    for (int j = 0; j < 8; j++) bb[j] = bias[n0 + tx * 8 + j];

#pragma unroll
    for (int ip = 0; ip < 4; ip++) {
#pragma unroll
        for (int j = 0; j < 8; j++) {
            float2 v2 = unpack2(acc2[ip][j]);
            int n = n0 + tx * 8 + j;
            float vr[2] = { v2.x + bb[j], v2.y + bb[j] };
#pragma unroll
            for (int hlf = 0; hlf < 2; hlf++) {
                int m = m0 + ty * 8 + ip * 2 + hlf;
                float v = vr[hlf];
                if (mode == 0) {
                    out[(size_t)m * Ee + n] = v;
                } else {
                    int b = m >> 12, s = m & 4095;
                    int h = n >> 6,  d = n & 63;
                    int bh = b * Hh + h;
                    if (mode == 1) {
                        g_Q[(((size_t)bh) * Ss + s) * Dd + d] = 0.125f * v;
                    } else if (mode == 2) {
                        g_K[(((size_t)bh) * LKV + Pp + s) * Dd + d] = v;
                    } else {
                        g_V[(((size_t)bh) * LKV + Pp + s) * Dd + d] = v;
                    }
                }
            }
        }
    }
}

__global__ __launch_bounds__(256, 2)
void sgemm_qkv(const float* __restrict__ query, const float* __restrict__ key,
               const float* __restrict__ value,
               const float* __restrict__ Wq, const float* __restrict__ bq,
               const float* __restrict__ Wk, const float* __restrict__ bk,
               const float* __restrict__ Wv, const float* __restrict__ bv)
{
    const int m0 = blockIdx.y * 128, n0 = blockIdx.x * 128;
    const int z = blockIdx.z;
    const float* A = (z == 0) ? query : (z == 1) ? key : value;
    const float* W = (z == 0) ? Wq : (z == 1) ? Wk : Wv;
    const float* bi = (z == 0) ? bq : (z == 1) ? bk : bv;
    sgemm_tile(A + (size_t)m0 * Ee, W + (size_t)n0 * Ee, bi, nullptr,
               m0, n0, z + 1);
}

__global__ __launch_bounds__(256, 2)
void sgemm_out(const float* __restrict__ Wo, const float* __restrict__ bo,
               float* __restrict__ out)
{
    const int m0 = blockIdx.y * 128, n0 = blockIdx.x * 128;
    sgemm_tile(g_ctx + (size_t)m0 * Ee, Wo + (size_t)n0 * Ee, bo, out,
               m0, n0, 0);
}

// ===========================================================================
// HMMA (mma.sync bf16) flash attention — FA2 register-resident design
// ===========================================================================

__device__ __forceinline__ u32 smem_u32(const void* p) {
    u32 a;
    asm("{ .reg .u64 t; cvta.to.shared.u64 t, %1; cvt.u32.u64 %0, t; }"
        : "=r"(a) : "l"(p));
    return a;
}
__device__ __forceinline__ void ldsm4(u32* r, u32 addr) {
    asm volatile("ldmatrix.sync.aligned.m8n8.x4.shared.b16 {%0,%1,%2,%3}, [%4];"
                 : "=r"(r[0]), "=r"(r[1]), "=r"(r[2]), "=r"(r[3]) : "r"(addr));
}
__device__ __forceinline__ void mma16816(float* c, const u32* a, u32 b0, u32 b1) {
    asm volatile(
        "mma.sync.aligned.m16n8k16.row.col.f32.bf16.bf16.f32 "
        "{%0,%1,%2,%3}, {%4,%5,%6,%7}, {%8,%9}, {%0,%1,%2,%3};"
        : "+f"(c[0]), "+f"(c[1]), "+f"(c[2]), "+f"(c[3])
        : "r"(a[0]), "r"(a[1]), "r"(a[2]), "r"(a[3]), "r"(b0), "r"(b1));
}
// hi/lo bf16 split of a float pair -> packed bf16x2 words (low half = first elem)
__device__ __forceinline__ void split2(float x0, float x1, u32& hi, u32& lo) {
    __nv_bfloat16 h0 = __float2bfloat16(x0), h1 = __float2bfloat16(x1);
    __nv_bfloat16 l0 = __float2bfloat16(x0 - __bfloat162float(h0));
    __nv_bfloat16 l1 = __float2bfloat16(x1 - __bfloat162float(h1));
    __nv_bfloat162 H; H.x = h0; H.y = h1;
    __nv_bfloat162 L; L.x = l0; L.y = l1;
    hi = *(u32*)&H; lo = *(u32*)&L;
}

// Smem byte offsets. Pitch = 72 halves (144 B) so ldmatrix rows land in
// distinct 16B bank groups. K stored [kv][d]; V stored transposed [d][kv];
// Q stored [q][d]. All as hi/lo bf16 tiles.
#define A_QH 0                    // 128*144 = 18432
#define A_QL 18432
#define A_KH 36864                // 64*144 = 9216
#define A_KL 46080
#define A_VH 55296
#define A_VL 64512
#define ATTN_SMEM 73728

__global__ __launch_bounds__(256, 1)
void attn_tc()
{
    extern __shared__ char smem[];
    const u32 sb = smem_u32(smem);
    const int tid = threadIdx.x, lane = tid & 31, warp = tid >> 5;
    const int qt = blockIdx.x, h = blockIdx.y, b = blockIdx.z;
    const int bh = b * Hh + h;
    const int m0 = warp * 16;                 // this warp's q-row base

    const float* Qg = g_Q + (((size_t)bh) * Ss + (size_t)qt * 128) * Dd;
    const float* Kg = g_K + ((size_t)bh) * LKV * Dd;
    const float* Vg = g_V + ((size_t)bh) * LKV * Dd;

    // ---- stage Q (128x64) hi/lo into smem [q][d], pitch 144B ----
#pragma unroll
    for (int it = 0; it < 8; it++) {
        int idx = it * 256 + tid;
        int r = idx >> 4, c4 = (idx & 15) << 2;
        float4 q4 = *(const float4*)(Qg + (size_t)r * Dd + c4);
        u32 hA, lA, hB, lB;
        split2(q4.x, q4.y, hA, lA);
        split2(q4.z, q4.w, hB, lB);
        u32 byte = (u32)r * 144 + (u32)c4 * 2;
        *(u32*)(smem + A_QH + byte)     = hA;
        *(u32*)(smem + A_QH + byte + 4) = hB;
        *(u32*)(smem + A_QL + byte)     = lA;
        *(u32*)(smem + A_QL + byte + 4) = lB;
    }
    __syncthreads();

    // ---- preload Q A-fragments (4 k-steps, hi+lo) ----
    u32 qh[4][4], ql[4][4];
    {
        u32 qrow = (u32)(m0 + (lane & 15));
        u32 qcol = (u32)((lane >> 4) << 3);   // 0 or 8 within k-slice
#pragma unroll
        for (int kk = 0; kk < 4; kk++) {
            u32 off = qrow * 144 + (kk * 16 + qcol) * 2;
            ldsm4(qh[kk], sb + A_QH + off);
            ldsm4(ql[kk], sb + A_QL + off);
        }
    }

    // O accumulators: 8 d-tiles x 4 f32
    float o[8][4];
#pragma unroll
    for (int j = 0; j < 8; j++)
#pragma unroll
        for (int x = 0; x < 4; x++) o[j][x] = 0.f;
    float l0 = 0.f, l1 = 0.f;

    // Per-lane ldmatrix source offsets for B-fragments (x4 = two n8 tiles)
    const u32 brow = (u32)((lane & 7) + ((lane & 16) >> 1));   // 0..15
    const u32 bcol = (u32)(lane & 8);                          // 0 or 8
    const int colbase = (lane & 3) * 2;

    const int NT = (LKV + 63) / 64;   // 65 tiles, last has 16 valid rows
    for (int t = 0; t < NT; t++) {
        const int kv0 = t * 64;
        __syncthreads();   // previous iteration's ldmatrix reads are done

        // ---- load K/V tile (64x64), split hi/lo; K natural, V transposed ----
#pragma unroll
        for (int it = 0; it < 4; it++) {
            int idx = it * 256 + tid;
            int r = idx >> 4, c4 = (idx & 15) << 2;
            int kv = kv0 + r;
            float4 k4, v4;
            if (kv < LKV) {
                k4 = *(const float4*)(Kg + (size_t)kv * Dd + c4);
                v4 = *(const float4*)(Vg + (size_t)kv * Dd + c4);
            } else {
                k4 = make_float4(0.f, 0.f, 0.f, 0.f);
                v4 = k4;
            }
            u32 hA, lA, hB, lB;
            split2(k4.x, k4.y, hA, lA);
            split2(k4.z, k4.w, hB, lB);
            u32 byte = (u32)r * 144 + (u32)c4 * 2;
            *(u32*)(smem + A_KH + byte)     = hA;
            *(u32*)(smem + A_KH + byte + 4) = hB;
            *(u32*)(smem + A_KL + byte)     = lA;
            *(u32*)(smem + A_KL + byte + 4) = lB;
            const float* vp = &v4.x;
#pragma unroll
            for (int jj = 0; jj < 4; jj++) {
                int d = c4 + jj;
                float x = vp[jj];
                __nv_bfloat16 hv = __float2bfloat16(x);
                __nv_bfloat16 lv = __float2bfloat16(x - __bfloat162float(hv));
                u32 vb = (u32)d * 144 + (u32)r * 2;
                *(__nv_bfloat16*)(smem + A_VH + vb) = hv;
                *(__nv_bfloat16*)(smem + A_VL + vb) = lv;
            }
        }
        __syncthreads();

        // ---- S = Q K^T : 8 n8-tiles x 4 k-steps x 3 split-products ----
        float sc[8][4];
#pragma unroll
        for (int j = 0; j < 8; j++)
#pragma unroll
            for (int x = 0; x < 4; x++) sc[j][x] = 0.f;

#pragma unroll
        for (int kk = 0; kk < 4; kk++) {
#pragma unroll
            for (int jp = 0; jp < 4; jp++) {
                u32 koff = (u32)(16 * jp + brow) * 144 + (kk * 16 + bcol) * 2;
                u32 bhh[4], bll[4];
                ldsm4(bhh, sb + A_KH + koff);
                ldsm4(bll, sb + A_KL + koff);
                mma16816(sc[2 * jp],     qh[kk], bhh[0], bhh[1]);
                mma16816(sc[2 * jp],     qh[kk], bll[0], bll[1]);
                mma16816(sc[2 * jp],     ql[kk], bhh[0], bhh[1]);
                mma16816(sc[2 * jp + 1], qh[kk], bhh[2], bhh[3]);
                mma16816(sc[2 * jp + 1], qh[kk], bll[2], bll[3]);
                mma16816(sc[2 * jp + 1], ql[kk], bhh[2], bhh[3]);
            }
        }

        // ---- shift-free softmax + in-register bf16 hi/lo P fragments ----
        u32 ph[4][4], pl[4][4];
        const bool last = (t == NT - 1);
#pragma unroll
        for (int j = 0; j < 8; j++) {
            float p0 = __expf(sc[j][0]);
            float p1 = __expf(sc[j][1]);
            float p2 = __expf(sc[j][2]);
            float p3 = __expf(sc[j][3]);
            if (last) {
                int c0 = kv0 + 8 * j + colbase;
                if (c0     >= LKV) { p0 = 0.f; p2 = 0.f; }
                if (c0 + 1 >= LKV) { p1 = 0.f; p3 = 0.f; }
            }
            l0 += p0 + p1;
            l1 += p2 + p3;
            int kk = j >> 1, hh = (j & 1) * 2;
            split2(p0, p1, ph[kk][hh],     pl[kk][hh]);
            split2(p2, p3, ph[kk][hh + 1], pl[kk][hh + 1]);
        }

        // ---- O += P V : 8 d-tiles x 4 kv-steps x 3 split-products ----
#pragma unroll
        for (int kk = 0; kk < 4; kk++) {
#pragma unroll
            for (int jp = 0; jp < 4; jp++) {
                u32 voff = (u32)(16 * jp + brow) * 144 + (kk * 16 + bcol) * 2;
                u32 bvh[4], bvl[4];
                ldsm4(bvh, sb + A_VH + voff);
                ldsm4(bvl, sb + A_VL + voff);
                mma16816(o[2 * jp],     ph[kk], bvh[0], bvh[1]);
                mma16816(o[2 * jp],     ph[kk], bvl[0], bvl[1]);
                mma16816(o[2 * jp],     pl[kk], bvh[0], bvh[1]);
                mma16816(o[2 * jp + 1], ph[kk], bvh[2], bvh[3]);
                mma16816(o[2 * jp + 1], ph[kk], bvl[2], bvl[3]);
                mma16816(o[2 * jp + 1], pl[kk], bvh[2], bvh[3]);
            }
        }
    }

    // ---- finalize: reduce l across the quad, normalize, store ----
    l0 += __shfl_xor_sync(0xffffffffu, l0, 1);
    l0 += __shfl_xor_sync(0xffffffffu, l0, 2);
    l1 += __shfl_xor_sync(0xffffffffu, l1, 1);
    l1 += __shfl_xor_sync(0xffffffffu, l1, 2);
    float i0 = 1.f / l0, i1 = 1.f / l1;

    int qrow = qt * 128 + m0 + (lane >> 2);
    float* C0 = g_ctx + ((size_t)b * Ss + qrow) * Ee + h * 64 + colbase;
    float* C1 = C0 + 8 * Ee;
#pragma unroll
    for (int j = 0; j < 8; j++) {
        float2 v0 = make_float2(o[j][0] * i0, o[j][1] * i0);
        float2 v1 = make_float2(o[j][2] * i1, o[j][3] * i1);
        *(float2*)(C0 + 8 * j) = v0;
        *(float2*)(C1 + 8 * j) = v1;
    }
}

// ---------------------------------------------------------------------------
extern "C" void kernel_launch(void* const* d_in, const int* in_sizes, int n_in,
                              void* d_out, int out_size)
{
    const float* query  = (const float*)d_in[0];
    const float* key    = (const float*)d_in[1];
    const float* value  = (const float*)d_in[2];
    const float* prompt = (const float*)d_in[3];
    const float* Wq = (const float*)d_in[4];
    const float* bq = (const float*)d_in[5];
    const float* Wk = (const float*)d_in[6];
    const float* bk = (const float*)d_in[7];
    const float* Wv = (const float*)d_in[8];
    const float* bv = (const float*)d_in[9];
    const float* Wo = (const float*)d_in[10];
    const float* bo = (const float*)d_in[11];
    float* out = (float*)d_out;

    cudaFuncSetAttribute(attn_tc, cudaFuncAttributeMaxDynamicSharedMemorySize, ATTN_SMEM);

    fill_prompt<<<(Bb * Pp * Hh * Dd + 255) / 256, 256>>>(prompt);

    dim3 gg(Ee / 128, (Bb * Ss) / 128, 3);
    sgemm_qkv<<<gg, 256>>>(query, key, value, Wq, bq, Wk, bk, Wv, bv);

    attn_tc<<<dim3(Ss / 128, Hh, Bb), 256, ATTN_SMEM>>>();

    sgemm_out<<<dim3(Ee / 128, (Bb * Ss) / 128), 256>>>(Wo, bo, out);
}

// round 11
// speedup vs baseline: 1.9384x; 1.3350x over previous
#include <cuda_runtime.h>
#include <cuda_bf16.h>
#include <math.h>
#include <cstdint>

// Problem constants
#define Bb   2
#define Ss   4096
#define Ee   768
#define Hh   12
#define Dd   64
#define Pp   16
#define LKV  4112            // Pp + Ss
#define BH   24              // Bb*Hh

typedef unsigned long long u64;
typedef unsigned int u32;

// Scratch (device globals: no allocation allowed)
__device__ float g_Q[(size_t)BH * Ss * Dd];     // [bh][s][d], pre-scaled by 1/8
__device__ float g_K[(size_t)BH * LKV * Dd];    // [bh][p+s][d]
__device__ float g_V[(size_t)BH * LKV * Dd];
__device__ float g_ctx[(size_t)Bb * Ss * Ee];   // [b][s][h*64+d]

// ---------------------------------------------------------------------------
// Shared HMMA helpers (verified by the passing R7 attention kernel)
// ---------------------------------------------------------------------------
__device__ __forceinline__ u32 smem_u32(const void* p) {
    u32 a;
    asm("{ .reg .u64 t; cvta.to.shared.u64 t, %1; cvt.u32.u64 %0, t; }"
        : "=r"(a) : "l"(p));
    return a;
}
__device__ __forceinline__ void ldsm4(u32* r, u32 addr) {
    asm volatile("ldmatrix.sync.aligned.m8n8.x4.shared.b16 {%0,%1,%2,%3}, [%4];"
                 : "=r"(r[0]), "=r"(r[1]), "=r"(r[2]), "=r"(r[3]) : "r"(addr));
}
__device__ __forceinline__ void mma16816(float* c, const u32* a, u32 b0, u32 b1) {
    asm volatile(
        "mma.sync.aligned.m16n8k16.row.col.f32.bf16.bf16.f32 "
        "{%0,%1,%2,%3}, {%4,%5,%6,%7}, {%8,%9}, {%0,%1,%2,%3};"
        : "+f"(c[0]), "+f"(c[1]), "+f"(c[2]), "+f"(c[3])
        : "r"(a[0]), "r"(a[1]), "r"(a[2]), "r"(a[3]), "r"(b0), "r"(b1));
}
// hi/lo bf16 split of a float pair -> packed bf16x2 words (low half = first elem)
__device__ __forceinline__ void split2(float x0, float x1, u32& hi, u32& lo) {
    __nv_bfloat16 h0 = __float2bfloat16(x0), h1 = __float2bfloat16(x1);
    __nv_bfloat16 l0 = __float2bfloat16(x0 - __bfloat162float(h0));
    __nv_bfloat16 l1 = __float2bfloat16(x1 - __bfloat162float(h1));
    __nv_bfloat162 H; H.x = h0; H.y = h1;
    __nv_bfloat162 L; L.x = l0; L.y = l1;
    hi = *(u32*)&H; lo = *(u32*)&L;
}

// ---------------------------------------------------------------------------
// Prompt prefix scatter
// ---------------------------------------------------------------------------
__global__ void fill_prompt(const float* __restrict__ prompt) {
    int i = blockIdx.x * 256 + threadIdx.x;
    if (i >= Bb * Pp * Hh * Dd) return;
    int d = i & 63;
    int h = (i >> 6) % Hh;
    int p = (i >> 6) / Hh % Pp;
    int b = i / (64 * Hh * Pp);
    size_t src0 = ((((size_t)b * 2 + 0) * Pp + p) * Hh + h) * Dd + d;
    size_t src1 = ((((size_t)b * 2 + 1) * Pp + p) * Hh + h) * Dd + d;
    size_t dst  = (((size_t)(b * Hh + h)) * LKV + p) * Dd + d;
    g_K[dst] = prompt[src0];
    g_V[dst] = prompt[src1];
}

// ---------------------------------------------------------------------------
// HMMA NT GEMM: C[128,128] tile of A[M,768] @ W[N,768]^T + bias
// bf16 hi/lo 3-product. 256 thr, 8 warps a 32x64. k-slice 32.
// Smem pitch = 40 halves (80 B): rows hit 8 distinct 16B bank groups.
// mode 0: out[m*768+n]   1: g_Q (x0.125, head layout)   2: g_K   3: g_V
// ---------------------------------------------------------------------------
#define GP 80          // pitch bytes
#define G_AH 0         // 128*80 = 10240 each
#define G_AL 10240
#define G_BH 20480
#define G_BL 30720

__device__ __forceinline__
void hgemm_tile(const float* __restrict__ Arow, const float* __restrict__ Brow,
                const float* __restrict__ bias, float* __restrict__ out,
                int m0, int n0, int mode, char* hs)
{
    const u32 sb = smem_u32(hs);
    const int tid = threadIdx.x, lane = tid & 31, warp = tid >> 5;
    const int wm = (warp & 3) * 32, wn = (warp >> 2) * 64;

    const u32 arow_l = (u32)(wm + (lane & 15));
    const u32 acol_l = (u32)((lane >> 4) << 3);
    const u32 brow_l = (u32)((lane & 7) + ((lane & 16) >> 1));
    const u32 bcol_l = (u32)(lane & 8);

    float acc[2][8][4];
#pragma unroll
    for (int a = 0; a < 2; a++)
#pragma unroll
        for (int u = 0; u < 8; u++)
#pragma unroll
            for (int x = 0; x < 4; x++) acc[a][u][x] = 0.f;

    for (int k0 = 0; k0 < Ee; k0 += 32) {
        // stage A,W (128x32 each) as bf16 hi/lo
#pragma unroll
        for (int it = 0; it < 4; it++) {
            int v = it * 256 + tid;
            int r = v >> 3, c4 = (v & 7) << 2;
            u32 byte = (u32)r * GP + (u32)c4 * 2;
            float4 ta = *(const float4*)(Arow + (size_t)r * Ee + k0 + c4);
            u32 hA, lA, hB, lB;
            split2(ta.x, ta.y, hA, lA);
            split2(ta.z, ta.w, hB, lB);
            *(u32*)(hs + G_AH + byte)     = hA;
            *(u32*)(hs + G_AH + byte + 4) = hB;
            *(u32*)(hs + G_AL + byte)     = lA;
            *(u32*)(hs + G_AL + byte + 4) = lB;
            float4 tb = *(const float4*)(Brow + (size_t)r * Ee + k0 + c4);
            split2(tb.x, tb.y, hA, lA);
            split2(tb.z, tb.w, hB, lB);
            *(u32*)(hs + G_BH + byte)     = hA;
            *(u32*)(hs + G_BH + byte + 4) = hB;
            *(u32*)(hs + G_BL + byte)     = lA;
            *(u32*)(hs + G_BL + byte + 4) = lB;
        }
        __syncthreads();

#pragma unroll
        for (int kk = 0; kk < 2; kk++) {
            u32 ah[2][4], al[2][4];
#pragma unroll
            for (int a = 0; a < 2; a++) {
                u32 off = (arow_l + a * 16) * GP + (kk * 16 + acol_l) * 2;
                ldsm4(ah[a], sb + G_AH + off);
                ldsm4(al[a], sb + G_AL + off);
            }
#pragma unroll
            for (int jp = 0; jp < 4; jp++) {
                u32 off = (u32)(wn + jp * 16 + brow_l) * GP + (kk * 16 + bcol_l) * 2;
                u32 bh4[4], bl4[4];
                ldsm4(bh4, sb + G_BH + off);
                ldsm4(bl4, sb + G_BL + off);
#pragma unroll
                for (int a = 0; a < 2; a++) {
                    mma16816(acc[a][2 * jp],     ah[a], bh4[0], bh4[1]);
                    mma16816(acc[a][2 * jp],     ah[a], bl4[0], bl4[1]);
                    mma16816(acc[a][2 * jp],     al[a], bh4[0], bh4[1]);
                    mma16816(acc[a][2 * jp + 1], ah[a], bh4[2], bh4[3]);
                    mma16816(acc[a][2 * jp + 1], ah[a], bl4[2], bl4[3]);
                    mma16816(acc[a][2 * jp + 1], al[a], bh4[2], bh4[3]);
                }
            }
        }
        __syncthreads();
    }

    // epilogue: C-fragment c0,c1 -> row (lane>>2); c2,c3 -> row+8; cols (lane&3)*2,+1
#pragma unroll
    for (int a = 0; a < 2; a++) {
        int mrow = m0 + wm + a * 16 + (lane >> 2);
#pragma unroll
        for (int u = 0; u < 8; u++) {
            int jp = u >> 1, half = u & 1;
            int n = n0 + wn + jp * 16 + half * 8 + (lane & 3) * 2;
            float bv0 = bias[n], bv1 = bias[n + 1];
            float c0 = acc[a][u][0] + bv0;
            float c1 = acc[a][u][1] + bv1;
            float c2 = acc[a][u][2] + bv0;
            float c3 = acc[a][u][3] + bv1;
            if (mode == 0) {
                *(float2*)(out + (size_t)mrow * Ee + n)       = make_float2(c0, c1);
                *(float2*)(out + (size_t)(mrow + 8) * Ee + n) = make_float2(c2, c3);
            } else {
                int hh = n >> 6, d = n & 63;
#pragma unroll
                for (int rr = 0; rr < 2; rr++) {
                    int m = mrow + rr * 8;
                    int bi = m >> 12, s = m & 4095;
                    int bh = bi * Hh + hh;
                    float v0 = rr ? c2 : c0, v1 = rr ? c3 : c1;
                    if (mode == 1) {
                        float2* p = (float2*)&g_Q[(((size_t)bh) * Ss + s) * Dd + d];
                        *p = make_float2(0.125f * v0, 0.125f * v1);
                    } else if (mode == 2) {
                        float2* p = (float2*)&g_K[(((size_t)bh) * LKV + Pp + s) * Dd + d];
                        *p = make_float2(v0, v1);
                    } else {
                        float2* p = (float2*)&g_V[(((size_t)bh) * LKV + Pp + s) * Dd + d];
                        *p = make_float2(v0, v1);
                    }
                }
            }
        }
    }
}

__global__ __launch_bounds__(256, 2)
void hgemm_qkv(const float* __restrict__ query, const float* __restrict__ key,
               const float* __restrict__ value,
               const float* __restrict__ Wq, const float* __restrict__ bq,
               const float* __restrict__ Wk, const float* __restrict__ bk,
               const float* __restrict__ Wv, const float* __restrict__ bv)
{
    __shared__ char hs[40960];
    const int m0 = blockIdx.y * 128, n0 = blockIdx.x * 128;
    const int z = blockIdx.z;
    const float* A = (z == 0) ? query : (z == 1) ? key : value;
    const float* W = (z == 0) ? Wq : (z == 1) ? Wk : Wv;
    const float* bi = (z == 0) ? bq : (z == 1) ? bk : bv;
    hgemm_tile(A + (size_t)m0 * Ee, W + (size_t)n0 * Ee, bi, nullptr,
               m0, n0, z + 1, hs);
}

__global__ __launch_bounds__(256, 2)
void hgemm_out(const float* __restrict__ Wo, const float* __restrict__ bo,
               float* __restrict__ out)
{
    __shared__ char hs[40960];
    const int m0 = blockIdx.y * 128, n0 = blockIdx.x * 128;
    hgemm_tile(g_ctx + (size_t)m0 * Ee, Wo + (size_t)n0 * Ee, bo, out,
               m0, n0, 0, hs);
}

// ===========================================================================
// HMMA (mma.sync bf16) flash attention — unchanged from passing R7 kernel
// ===========================================================================

// Smem byte offsets. Pitch = 72 halves (144 B). K stored [kv][d]; V stored
// transposed [d][kv]; Q stored [q][d]. All as hi/lo bf16 tiles.
#define A_QH 0                    // 128*144 = 18432
#define A_QL 18432
#define A_KH 36864                // 64*144 = 9216
#define A_KL 46080
#define A_VH 55296
#define A_VL 64512
#define ATTN_SMEM 73728

__global__ __launch_bounds__(256, 1)
void attn_tc()
{
    extern __shared__ char smem[];
    const u32 sb = smem_u32(smem);
    const int tid = threadIdx.x, lane = tid & 31, warp = tid >> 5;
    const int qt = blockIdx.x, h = blockIdx.y, b = blockIdx.z;
    const int bh = b * Hh + h;
    const int m0 = warp * 16;                 // this warp's q-row base

    const float* Qg = g_Q + (((size_t)bh) * Ss + (size_t)qt * 128) * Dd;
    const float* Kg = g_K + ((size_t)bh) * LKV * Dd;
    const float* Vg = g_V + ((size_t)bh) * LKV * Dd;

    // ---- stage Q (128x64) hi/lo into smem [q][d], pitch 144B ----
#pragma unroll
    for (int it = 0; it < 8; it++) {
        int idx = it * 256 + tid;
        int r = idx >> 4, c4 = (idx & 15) << 2;
        float4 q4 = *(const float4*)(Qg + (size_t)r * Dd + c4);
        u32 hA, lA, hB, lB;
        split2(q4.x, q4.y, hA, lA);
        split2(q4.z, q4.w, hB, lB);
        u32 byte = (u32)r * 144 + (u32)c4 * 2;
        *(u32*)(smem + A_QH + byte)     = hA;
        *(u32*)(smem + A_QH + byte + 4) = hB;
        *(u32*)(smem + A_QL + byte)     = lA;
        *(u32*)(smem + A_QL + byte + 4) = lB;
    }
    __syncthreads();

    // ---- preload Q A-fragments (4 k-steps, hi+lo) ----
    u32 qh[4][4], ql[4][4];
    {
        u32 qrow = (u32)(m0 + (lane & 15));
        u32 qcol = (u32)((lane >> 4) << 3);   // 0 or 8 within k-slice
#pragma unroll
        for (int kk = 0; kk < 4; kk++) {
            u32 off = qrow * 144 + (kk * 16 + qcol) * 2;
            ldsm4(qh[kk], sb + A_QH + off);
            ldsm4(ql[kk], sb + A_QL + off);
        }
    }

    // O accumulators: 8 d-tiles x 4 f32
    float o[8][4];
#pragma unroll
    for (int j = 0; j < 8; j++)
#pragma unroll
        for (int x = 0; x < 4; x++) o[j][x] = 0.f;
    float l0 = 0.f, l1 = 0.f;

    // Per-lane ldmatrix source offsets for B-fragments (x4 = two n8 tiles)
    const u32 brow = (u32)((lane & 7) + ((lane & 16) >> 1));   // 0..15
    const u32 bcol = (u32)(lane & 8);                          // 0 or 8
    const int colbase = (lane & 3) * 2;

    const int NT = (LKV + 63) / 64;   // 65 tiles, last has 16 valid rows
    for (int t = 0; t < NT; t++) {
        const int kv0 = t * 64;
        __syncthreads();   // previous iteration's ldmatrix reads are done

        // ---- load K/V tile (64x64), split hi/lo; K natural, V transposed ----
#pragma unroll
        for (int it = 0; it < 4; it++) {
            int idx = it * 256 + tid;
            int r = idx >> 4, c4 = (idx & 15) << 2;
            int kv = kv0 + r;
            float4 k4, v4;
            if (kv < LKV) {
                k4 = *(const float4*)(Kg + (size_t)kv * Dd + c4);
                v4 = *(const float4*)(Vg + (size_t)kv * Dd + c4);
            } else {
                k4 = make_float4(0.f, 0.f, 0.f, 0.f);
                v4 = k4;
            }
            u32 hA, lA, hB, lB;
            split2(k4.x, k4.y, hA, lA);
            split2(k4.z, k4.w, hB, lB);
            u32 byte = (u32)r * 144 + (u32)c4 * 2;
            *(u32*)(smem + A_KH + byte)     = hA;
            *(u32*)(smem + A_KH + byte + 4) = hB;
            *(u32*)(smem + A_KL + byte)     = lA;
            *(u32*)(smem + A_KL + byte + 4) = lB;
            const float* vp = &v4.x;
#pragma unroll
            for (int jj = 0; jj < 4; jj++) {
                int d = c4 + jj;
                float x = vp[jj];
                __nv_bfloat16 hv = __float2bfloat16(x);
                __nv_bfloat16 lv = __float2bfloat16(x - __bfloat162float(hv));
                u32 vb = (u32)d * 144 + (u32)r * 2;
                *(__nv_bfloat16*)(smem + A_VH + vb) = hv;
                *(__nv_bfloat16*)(smem + A_VL + vb) = lv;
            }
        }
        __syncthreads();

        // ---- S = Q K^T : 8 n8-tiles x 4 k-steps x 3 split-products ----
        float sc[8][4];
#pragma unroll
        for (int j = 0; j < 8; j++)
#pragma unroll
            for (int x = 0; x < 4; x++) sc[j][x] = 0.f;

#pragma unroll
        for (int kk = 0; kk < 4; kk++) {
#pragma unroll
            for (int jp = 0; jp < 4; jp++) {
                u32 koff = (u32)(16 * jp + brow) * 144 + (kk * 16 + bcol) * 2;
                u32 bhh[4], bll[4];
                ldsm4(bhh, sb + A_KH + koff);
                ldsm4(bll, sb + A_KL + koff);
                mma16816(sc[2 * jp],     qh[kk], bhh[0], bhh[1]);
                mma16816(sc[2 * jp],     qh[kk], bll[0], bll[1]);
                mma16816(sc[2 * jp],     ql[kk], bhh[0], bhh[1]);
                mma16816(sc[2 * jp + 1], qh[kk], bhh[2], bhh[3]);
                mma16816(sc[2 * jp + 1], qh[kk], bll[2], bll[3]);
                mma16816(sc[2 * jp + 1], ql[kk], bhh[2], bhh[3]);
            }
        }

        // ---- shift-free softmax + in-register bf16 hi/lo P fragments ----
        u32 ph[4][4], pl[4][4];
        const bool last = (t == NT - 1);
#pragma unroll
        for (int j = 0; j < 8; j++) {
            float p0 = __expf(sc[j][0]);
            float p1 = __expf(sc[j][1]);
            float p2 = __expf(sc[j][2]);
            float p3 = __expf(sc[j][3]);
            if (last) {
                int c0 = kv0 + 8 * j + colbase;
                if (c0     >= LKV) { p0 = 0.f; p2 = 0.f; }
                if (c0 + 1 >= LKV) { p1 = 0.f; p3 = 0.f; }
            }
            l0 += p0 + p1;
            l1 += p2 + p3;
            int kk = j >> 1, hh = (j & 1) * 2;
            split2(p0, p1, ph[kk][hh],     pl[kk][hh]);
            split2(p2, p3, ph[kk][hh + 1], pl[kk][hh + 1]);
        }

        // ---- O += P V : 8 d-tiles x 4 kv-steps x 3 split-products ----
#pragma unroll
        for (int kk = 0; kk < 4; kk++) {
#pragma unroll
            for (int jp = 0; jp < 4; jp++) {
                u32 voff = (u32)(16 * jp + brow) * 144 + (kk * 16 + bcol) * 2;
                u32 bvh[4], bvl[4];
                ldsm4(bvh, sb + A_VH + voff);
                ldsm4(bvl, sb + A_VL + voff);
                mma16816(o[2 * jp],     ph[kk], bvh[0], bvh[1]);
                mma16816(o[2 * jp],     ph[kk], bvl[0], bvl[1]);
                mma16816(o[2 * jp],     pl[kk], bvh[0], bvh[1]);
                mma16816(o[2 * jp + 1], ph[kk], bvh[2], bvh[3]);
                mma16816(o[2 * jp + 1], ph[kk], bvl[2], bvl[3]);
                mma16816(o[2 * jp + 1], pl[kk], bvh[2], bvh[3]);
            }
        }
    }

    // ---- finalize: reduce l across the quad, normalize, store ----
    l0 += __shfl_xor_sync(0xffffffffu, l0, 1);
    l0 += __shfl_xor_sync(0xffffffffu, l0, 2);
    l1 += __shfl_xor_sync(0xffffffffu, l1, 1);
    l1 += __shfl_xor_sync(0xffffffffu, l1, 2);
    float i0 = 1.f / l0, i1 = 1.f / l1;

    int qrow = qt * 128 + m0 + (lane >> 2);
    float* C0 = g_ctx + ((size_t)b * Ss + qrow) * Ee + h * 64 + colbase;
    float* C1 = C0 + 8 * Ee;
#pragma unroll
    for (int j = 0; j < 8; j++) {
        float2 v0 = make_float2(o[j][0] * i0, o[j][1] * i0);
        float2 v1 = make_float2(o[j][2] * i1, o[j][3] * i1);
        *(float2*)(C0 + 8 * j) = v0;
        *(float2*)(C1 + 8 * j) = v1;
    }
}

// ---------------------------------------------------------------------------
extern "C" void kernel_launch(void* const* d_in, const int* in_sizes, int n_in,
                              void* d_out, int out_size)
{
    const float* query  = (const float*)d_in[0];
    const float* key    = (const float*)d_in[1];
    const float* value  = (const float*)d_in[2];
    const float* prompt = (const float*)d_in[3];
    const float* Wq = (const float*)d_in[4];
    const float* bq = (const float*)d_in[5];
    const float* Wk = (const float*)d_in[6];
    const float* bk = (const float*)d_in[7];
    const float* Wv = (const float*)d_in[8];
    const float* bv = (const float*)d_in[9];
    const float* Wo = (const float*)d_in[10];
    const float* bo = (const float*)d_in[11];
    float* out = (float*)d_out;

    cudaFuncSetAttribute(attn_tc, cudaFuncAttributeMaxDynamicSharedMemorySize, ATTN_SMEM);

    fill_prompt<<<(Bb * Pp * Hh * Dd + 255) / 256, 256>>>(prompt);

    dim3 gg(Ee / 128, (Bb * Ss) / 128, 3);
    hgemm_qkv<<<gg, 256>>>(query, key, value, Wq, bq, Wk, bk, Wv, bv);

    attn_tc<<<dim3(Ss / 128, Hh, Bb), 256, ATTN_SMEM>>>();

    hgemm_out<<<dim3(Ee / 128, (Bb * Ss) / 128), 256>>>(Wo, bo, out);
}

// round 15
// speedup vs baseline: 2.9143x; 1.5035x over previous
#include <cuda_runtime.h>
#include <cuda_bf16.h>
#include <math.h>
#include <cstdint>

// Problem constants
#define Bb   2
#define Ss   4096
#define Ee   768
#define Hh   12
#define Dd   64
#define Pp   16
#define LKV  4112            // Pp + Ss
#define BH   24              // Bb*Hh

typedef unsigned long long u64;
typedef unsigned int u32;

// Scratch (device globals: no allocation allowed). Q/K as [..][row][d] bf16
// hi/lo pairs; V pre-transposed [bh][d][kv]. Padded so the last attention
// tile's OOB cp.async reads stay inside the arrays (zero-initialized).
__device__ __nv_bfloat16 g_Qh[(size_t)BH * Ss * Dd];
__device__ __nv_bfloat16 g_Ql[(size_t)BH * Ss * Dd];
__device__ __nv_bfloat16 g_Kh[(size_t)BH * LKV * Dd + 64 * Dd];
__device__ __nv_bfloat16 g_Kl[(size_t)BH * LKV * Dd + 64 * Dd];
__device__ __nv_bfloat16 g_Vth[(size_t)BH * Dd * LKV + 64 * Dd];
__device__ __nv_bfloat16 g_Vtl[(size_t)BH * Dd * LKV + 64 * Dd];
__device__ float g_ctx[(size_t)Bb * Ss * Ee];   // [b][s][h*64+d]

// ---------------------------------------------------------------------------
// Shared HMMA / async helpers
// ---------------------------------------------------------------------------
__device__ __forceinline__ u32 smem_u32(const void* p) {
    u32 a;
    asm("{ .reg .u64 t; cvta.to.shared.u64 t, %1; cvt.u32.u64 %0, t; }"
        : "=r"(a) : "l"(p));
    return a;
}
__device__ __forceinline__ void ldsm4(u32* r, u32 addr) {
    asm volatile("ldmatrix.sync.aligned.m8n8.x4.shared.b16 {%0,%1,%2,%3}, [%4];"
                 : "=r"(r[0]), "=r"(r[1]), "=r"(r[2]), "=r"(r[3]) : "r"(addr));
}
__device__ __forceinline__ void mma16816(float* c, const u32* a, u32 b0, u32 b1) {
    asm volatile(
        "mma.sync.aligned.m16n8k16.row.col.f32.bf16.bf16.f32 "
        "{%0,%1,%2,%3}, {%4,%5,%6,%7}, {%8,%9}, {%0,%1,%2,%3};"
        : "+f"(c[0]), "+f"(c[1]), "+f"(c[2]), "+f"(c[3])
        : "r"(a[0]), "r"(a[1]), "r"(a[2]), "r"(a[3]), "r"(b0), "r"(b1));
}
__device__ __forceinline__ void cp16(u32 dst, const void* src) {
    asm volatile("cp.async.ca.shared.global [%0], [%1], 16;"
                 :: "r"(dst), "l"(src) : "memory");
}
#define CP_COMMIT() asm volatile("cp.async.commit_group;" ::: "memory")
#define CP_WAIT0()  asm volatile("cp.async.wait_group 0;" ::: "memory")

// hi/lo bf16 split of a float pair -> packed bf16x2 words (low half = first elem)
__device__ __forceinline__ void split2(float x0, float x1, u32& hi, u32& lo) {
    __nv_bfloat16 h0 = __float2bfloat16(x0), h1 = __float2bfloat16(x1);
    __nv_bfloat16 l0 = __float2bfloat16(x0 - __bfloat162float(h0));
    __nv_bfloat16 l1 = __float2bfloat16(x1 - __bfloat162float(h1));
    __nv_bfloat162 H; H.x = h0; H.y = h1;
    __nv_bfloat162 L; L.x = l0; L.y = l1;
    hi = *(u32*)&H; lo = *(u32*)&L;
}

// ---------------------------------------------------------------------------
// Prompt prefix scatter (writes bf16 hi/lo; V transposed)
// ---------------------------------------------------------------------------
__global__ void fill_prompt(const float* __restrict__ prompt) {
    int i = blockIdx.x * 256 + threadIdx.x;
    if (i >= Bb * Pp * Hh * Dd) return;
    int d = i & 63;
    int h = (i >> 6) % Hh;
    int p = (i >> 6) / Hh % Pp;
    int b = i / (64 * Hh * Pp);
    int bh = b * Hh + h;
    float kx = prompt[((((size_t)b * 2 + 0) * Pp + p) * Hh + h) * Dd + d];
    float vx = prompt[((((size_t)b * 2 + 1) * Pp + p) * Hh + h) * Dd + d];
    __nv_bfloat16 kh = __float2bfloat16(kx);
    __nv_bfloat16 kl = __float2bfloat16(kx - __bfloat162float(kh));
    __nv_bfloat16 vh = __float2bfloat16(vx);
    __nv_bfloat16 vl = __float2bfloat16(vx - __bfloat162float(vh));
    size_t ki = (((size_t)bh) * LKV + p) * Dd + d;
    g_Kh[ki] = kh; g_Kl[ki] = kl;
    size_t vi = (((size_t)bh) * Dd + d) * LKV + p;
    g_Vth[vi] = vh; g_Vtl[vi] = vl;
}

// ---------------------------------------------------------------------------
// HMMA NT GEMM (proven R11 core). Epilogues now emit pre-split bf16 Q/K/V.
// mode 0: out[m*768+n]  1: Q (x0.125 -> g_Qh/g_Ql)  2: K  3: V (transposed)
// ---------------------------------------------------------------------------
#define GP 80          // pitch bytes
#define G_AH 0         // 128*80 = 10240 each
#define G_AL 10240
#define G_BH 20480
#define G_BL 30720

__device__ __forceinline__
void hgemm_tile(const float* __restrict__ Arow, const float* __restrict__ Brow,
                const float* __restrict__ bias, float* __restrict__ out,
                int m0, int n0, int mode, char* hs)
{
    const u32 sb = smem_u32(hs);
    const int tid = threadIdx.x, lane = tid & 31, warp = tid >> 5;
    const int wm = (warp & 3) * 32, wn = (warp >> 2) * 64;

    const u32 arow_l = (u32)(wm + (lane & 15));
    const u32 acol_l = (u32)((lane >> 4) << 3);
    const u32 brow_l = (u32)((lane & 7) + ((lane & 16) >> 1));
    const u32 bcol_l = (u32)(lane & 8);

    float acc[2][8][4];
#pragma unroll
    for (int a = 0; a < 2; a++)
#pragma unroll
        for (int u = 0; u < 8; u++)
#pragma unroll
            for (int x = 0; x < 4; x++) acc[a][u][x] = 0.f;

    for (int k0 = 0; k0 < Ee; k0 += 32) {
#pragma unroll
        for (int it = 0; it < 4; it++) {
            int v = it * 256 + tid;
            int r = v >> 3, c4 = (v & 7) << 2;
            u32 byte = (u32)r * GP + (u32)c4 * 2;
            float4 ta = *(const float4*)(Arow + (size_t)r * Ee + k0 + c4);
            u32 hA, lA, hB, lB;
            split2(ta.x, ta.y, hA, lA);
            split2(ta.z, ta.w, hB, lB);
            *(u32*)(hs + G_AH + byte)     = hA;
            *(u32*)(hs + G_AH + byte + 4) = hB;
            *(u32*)(hs + G_AL + byte)     = lA;
            *(u32*)(hs + G_AL + byte + 4) = lB;
            float4 tb = *(const float4*)(Brow + (size_t)r * Ee + k0 + c4);
            split2(tb.x, tb.y, hA, lA);
            split2(tb.z, tb.w, hB, lB);
            *(u32*)(hs + G_BH + byte)     = hA;
            *(u32*)(hs + G_BH + byte + 4) = hB;
            *(u32*)(hs + G_BL + byte)     = lA;
            *(u32*)(hs + G_BL + byte + 4) = lB;
        }
        __syncthreads();

#pragma unroll
        for (int kk = 0; kk < 2; kk++) {
            u32 ah[2][4], al[2][4];
#pragma unroll
            for (int a = 0; a < 2; a++) {
                u32 off = (arow_l + a * 16) * GP + (kk * 16 + acol_l) * 2;
                ldsm4(ah[a], sb + G_AH + off);
                ldsm4(al[a], sb + G_AL + off);
            }
#pragma unroll
            for (int jp = 0; jp < 4; jp++) {
                u32 off = (u32)(wn + jp * 16 + brow_l) * GP + (kk * 16 + bcol_l) * 2;
                u32 bh4[4], bl4[4];
                ldsm4(bh4, sb + G_BH + off);
                ldsm4(bl4, sb + G_BL + off);
#pragma unroll
                for (int a = 0; a < 2; a++) {
                    mma16816(acc[a][2 * jp],     ah[a], bh4[0], bh4[1]);
                    mma16816(acc[a][2 * jp],     ah[a], bl4[0], bl4[1]);
                    mma16816(acc[a][2 * jp],     al[a], bh4[0], bh4[1]);
                    mma16816(acc[a][2 * jp + 1], ah[a], bh4[2], bh4[3]);
                    mma16816(acc[a][2 * jp + 1], ah[a], bl4[2], bl4[3]);
                    mma16816(acc[a][2 * jp + 1], al[a], bh4[2], bh4[3]);
                }
            }
        }
        __syncthreads();
    }

    // epilogue: c0,c1 -> row (lane>>2); c2,c3 -> row+8; cols (lane&3)*2,+1
#pragma unroll
    for (int a = 0; a < 2; a++) {
        int mrow = m0 + wm + a * 16 + (lane >> 2);
#pragma unroll
        for (int u = 0; u < 8; u++) {
            int jp = u >> 1, half = u & 1;
            int n = n0 + wn + jp * 16 + half * 8 + (lane & 3) * 2;
            float bv0 = bias[n], bv1 = bias[n + 1];
            float c0 = acc[a][u][0] + bv0;
            float c1 = acc[a][u][1] + bv1;
            float c2 = acc[a][u][2] + bv0;
            float c3 = acc[a][u][3] + bv1;
            if (mode == 0) {
                *(float2*)(out + (size_t)mrow * Ee + n)       = make_float2(c0, c1);
                *(float2*)(out + (size_t)(mrow + 8) * Ee + n) = make_float2(c2, c3);
            } else {
                int hh = n >> 6, d = n & 63;
#pragma unroll
                for (int rr = 0; rr < 2; rr++) {
                    int m = mrow + rr * 8;
                    int bi = m >> 12, s = m & 4095;
                    int bh = bi * Hh + hh;
                    float v0 = rr ? c2 : c0, v1 = rr ? c3 : c1;
                    if (mode == 1) {
                        u32 hq, lq;
                        split2(0.125f * v0, 0.125f * v1, hq, lq);
                        size_t idx = (((size_t)bh) * Ss + s) * Dd + d;
                        *(u32*)&g_Qh[idx] = hq;
                        *(u32*)&g_Ql[idx] = lq;
                    } else if (mode == 2) {
                        u32 hk, lk;
                        split2(v0, v1, hk, lk);
                        size_t idx = (((size_t)bh) * LKV + Pp + s) * Dd + d;
                        *(u32*)&g_Kh[idx] = hk;
                        *(u32*)&g_Kl[idx] = lk;
                    } else {
                        __nv_bfloat16 h0 = __float2bfloat16(v0);
                        __nv_bfloat16 l0v = __float2bfloat16(v0 - __bfloat162float(h0));
                        __nv_bfloat16 h1 = __float2bfloat16(v1);
                        __nv_bfloat16 l1v = __float2bfloat16(v1 - __bfloat162float(h1));
                        size_t i0 = (((size_t)bh) * Dd + d) * LKV + Pp + s;
                        size_t i1 = i0 + LKV;
                        g_Vth[i0] = h0; g_Vtl[i0] = l0v;
                        g_Vth[i1] = h1; g_Vtl[i1] = l1v;
                    }
                }
            }
        }
    }
}

__global__ __launch_bounds__(256, 2)
void hgemm_qkv(const float* __restrict__ query, const float* __restrict__ key,
               const float* __restrict__ value,
               const float* __restrict__ Wq, const float* __restrict__ bq,
               const float* __restrict__ Wk, const float* __restrict__ bk,
               const float* __restrict__ Wv, const float* __restrict__ bv)
{
    __shared__ char hs[40960];
    const int m0 = blockIdx.y * 128, n0 = blockIdx.x * 128;
    const int z = blockIdx.z;
    const float* A = (z == 0) ? query : (z == 1) ? key : value;
    const float* W = (z == 0) ? Wq : (z == 1) ? Wk : Wv;
    const float* bi = (z == 0) ? bq : (z == 1) ? bk : bv;
    hgemm_tile(A + (size_t)m0 * Ee, W + (size_t)n0 * Ee, bi, nullptr,
               m0, n0, z + 1, hs);
}

__global__ __launch_bounds__(256, 2)
void hgemm_out(const float* __restrict__ Wo, const float* __restrict__ bo,
               float* __restrict__ out)
{
    __shared__ char hs[40960];
    const int m0 = blockIdx.y * 128, n0 = blockIdx.x * 128;
    hgemm_tile(g_ctx + (size_t)m0 * Ee, Wo + (size_t)n0 * Ee, bo, out,
               m0, n0, 0, hs);
}

// ===========================================================================
// HMMA flash attention with pre-split bf16 inputs + cp.async double buffering
// ===========================================================================

// Smem: pitch 144 B rows. Q hi/lo [q][d]; per-stage K hi/lo [kv][d] and
// Vt hi/lo [d][kv].
#define A_QH 0                    // 128*144 = 18432
#define A_QL 18432
#define S_STG 36864               // stage base; each stage 4*9216 = 36864
#define SK_H 0
#define SK_L 9216
#define SV_H 18432
#define SV_L 27648
#define ATTN_SMEM (S_STG + 2 * 36864)   // 110592

__global__ __launch_bounds__(256, 1)
void attn_tc()
{
    extern __shared__ char smem[];
    const u32 sb = smem_u32(smem);
    const int tid = threadIdx.x, lane = tid & 31, warp = tid >> 5;
    const int qt = blockIdx.x, h = blockIdx.y, b = blockIdx.z;
    const int bh = b * Hh + h;
    const int m0 = warp * 16;                 // this warp's q-row base

    const __nv_bfloat16* Qh = g_Qh + (((size_t)bh) * Ss + (size_t)qt * 128) * Dd;
    const __nv_bfloat16* Ql = g_Ql + (((size_t)bh) * Ss + (size_t)qt * 128) * Dd;
    const __nv_bfloat16* Kh = g_Kh + ((size_t)bh) * LKV * Dd;
    const __nv_bfloat16* Kl = g_Kl + ((size_t)bh) * LKV * Dd;
    const __nv_bfloat16* Vh = g_Vth + ((size_t)bh) * Dd * LKV;
    const __nv_bfloat16* Vl = g_Vtl + ((size_t)bh) * Dd * LKV;

    const int NT = (LKV + 63) / 64;           // 65 tiles, last has 16 valid rows

    // issue async K/V tile t into stage buffer s (8 cp.async of 16B per thread)
    auto stage_kv = [&](int t, int s) {
        const int kv0 = t * 64;
        const u32 base = sb + S_STG + (u32)s * 36864;
#pragma unroll
        for (int i = 0; i < 2; i++) {
            int v = i * 256 + tid;
            int r = v >> 3, c = v & 7;
            u32 dst = (u32)r * 144 + (u32)c * 16;
            size_t koff = ((size_t)(kv0 + r)) * Dd + c * 8;
            cp16(base + SK_H + dst, Kh + koff);
            cp16(base + SK_L + dst, Kl + koff);
            size_t voff = ((size_t)r) * LKV + kv0 + c * 8;
            cp16(base + SV_H + dst, Vh + voff);
            cp16(base + SV_L + dst, Vl + voff);
        }
        CP_COMMIT();
    };

    // prefetch tile 0 while staging Q
    stage_kv(0, 0);

    // ---- stage Q (pure copy of pre-split bf16) ----
#pragma unroll
    for (int it = 0; it < 4; it++) {
        int v = it * 256 + tid;
        int r = v >> 3, c = v & 7;
        u32 dst = (u32)r * 144 + (u32)c * 16;
        *(uint4*)(smem + A_QH + dst) = *(const uint4*)(Qh + (size_t)r * Dd + c * 8);
        *(uint4*)(smem + A_QL + dst) = *(const uint4*)(Ql + (size_t)r * Dd + c * 8);
    }
    __syncthreads();

    // ---- preload Q A-fragments (4 k-steps, hi+lo) ----
    u32 qh[4][4], ql[4][4];
    {
        u32 qrow = (u32)(m0 + (lane & 15));
        u32 qcol = (u32)((lane >> 4) << 3);
#pragma unroll
        for (int kk = 0; kk < 4; kk++) {
            u32 off = qrow * 144 + (kk * 16 + qcol) * 2;
            ldsm4(qh[kk], sb + A_QH + off);
            ldsm4(ql[kk], sb + A_QL + off);
        }
    }

    float o[8][4];
#pragma unroll
    for (int j = 0; j < 8; j++)
#pragma unroll
        for (int x = 0; x < 4; x++) o[j][x] = 0.f;
    float l0 = 0.f, l1 = 0.f;

    const u32 brow = (u32)((lane & 7) + ((lane & 16) >> 1));   // 0..15
    const u32 bcol = (u32)(lane & 8);                          // 0 or 8
    const int colbase = (lane & 3) * 2;

    for (int t = 0; t < NT; t++) {
        const int kv0 = t * 64;
        CP_WAIT0();            // stage t&1 data landed
        __syncthreads();       // ...and prev compute done before reuse below
        if (t + 1 < NT) stage_kv(t + 1, (t + 1) & 1);

        const u32 kb = sb + S_STG + (u32)(t & 1) * 36864;

        // ---- S = Q K^T : 8 n8-tiles x 4 k-steps x 3 split-products ----
        float sc[8][4];
#pragma unroll
        for (int j = 0; j < 8; j++)
#pragma unroll
            for (int x = 0; x < 4; x++) sc[j][x] = 0.f;

#pragma unroll
        for (int kk = 0; kk < 4; kk++) {
#pragma unroll
            for (int jp = 0; jp < 4; jp++) {
                u32 koff = (u32)(16 * jp + brow) * 144 + (kk * 16 + bcol) * 2;
                u32 bhh[4], bll[4];
                ldsm4(bhh, kb + SK_H + koff);
                ldsm4(bll, kb + SK_L + koff);
                mma16816(sc[2 * jp],     qh[kk], bhh[0], bhh[1]);
                mma16816(sc[2 * jp],     qh[kk], bll[0], bll[1]);
                mma16816(sc[2 * jp],     ql[kk], bhh[0], bhh[1]);
                mma16816(sc[2 * jp + 1], qh[kk], bhh[2], bhh[3]);
                mma16816(sc[2 * jp + 1], qh[kk], bll[2], bll[3]);
                mma16816(sc[2 * jp + 1], ql[kk], bhh[2], bhh[3]);
            }
        }

        // ---- shift-free softmax + in-register bf16 hi/lo P fragments ----
        u32 ph[4][4], pl[4][4];
        const bool last = (t == NT - 1);
#pragma unroll
        for (int j = 0; j < 8; j++) {
            float p0 = __expf(sc[j][0]);
            float p1 = __expf(sc[j][1]);
            float p2 = __expf(sc[j][2]);
            float p3 = __expf(sc[j][3]);
            if (last) {
                int c0 = kv0 + 8 * j + colbase;
                if (c0     >= LKV) { p0 = 0.f; p2 = 0.f; }
                if (c0 + 1 >= LKV) { p1 = 0.f; p3 = 0.f; }
            }
            l0 += p0 + p1;
            l1 += p2 + p3;
            int kk = j >> 1, hh = (j & 1) * 2;
            split2(p0, p1, ph[kk][hh],     pl[kk][hh]);
            split2(p2, p3, ph[kk][hh + 1], pl[kk][hh + 1]);
        }

        // ---- O += P V : 8 d-tiles x 4 kv-steps x 3 split-products ----
#pragma unroll
        for (int kk = 0; kk < 4; kk++) {
#pragma unroll
            for (int jp = 0; jp < 4; jp++) {
                u32 voff = (u32)(16 * jp + brow) * 144 + (kk * 16 + bcol) * 2;
                u32 bvh[4], bvl[4];
                ldsm4(bvh, kb + SV_H + voff);
                ldsm4(bvl, kb + SV_L + voff);
                mma16816(o[2 * jp],     ph[kk], bvh[0], bvh[1]);
                mma16816(o[2 * jp],     ph[kk], bvl[0], bvl[1]);
                mma16816(o[2 * jp],     pl[kk], bvh[0], bvh[1]);
                mma16816(o[2 * jp + 1], ph[kk], bvh[2], bvh[3]);
                mma16816(o[2 * jp + 1], ph[kk], bvl[2], bvl[3]);
                mma16816(o[2 * jp + 1], pl[kk], bvh[2], bvh[3]);
            }
        }
    }

    // ---- finalize: reduce l across the quad, normalize, store ----
    l0 += __shfl_xor_sync(0xffffffffu, l0, 1);
    l0 += __shfl_xor_sync(0xffffffffu, l0, 2);
    l1 += __shfl_xor_sync(0xffffffffu, l1, 1);
    l1 += __shfl_xor_sync(0xffffffffu, l1, 2);
    float i0 = 1.f / l0, i1 = 1.f / l1;

    int qrow = qt * 128 + m0 + (lane >> 2);
    float* C0 = g_ctx + ((size_t)b * Ss + qrow) * Ee + h * 64 + colbase;
    float* C1 = C0 + 8 * Ee;
#pragma unroll
    for (int j = 0; j < 8; j++) {
        float2 v0 = make_float2(o[j][0] * i0, o[j][1] * i0);
        float2 v1 = make_float2(o[j][2] * i1, o[j][3] * i1);
        *(float2*)(C0 + 8 * j) = v0;
        *(float2*)(C1 + 8 * j) = v1;
    }
}

// ---------------------------------------------------------------------------
extern "C" void kernel_launch(void* const* d_in, const int* in_sizes, int n_in,
                              void* d_out, int out_size)
{
    const float* query  = (const float*)d_in[0];
    const float* key    = (const float*)d_in[1];
    const float* value  = (const float*)d_in[2];
    const float* prompt = (const float*)d_in[3];
    const float* Wq = (const float*)d_in[4];
    const float* bq = (const float*)d_in[5];
    const float* Wk = (const float*)d_in[6];
    const float* bk = (const float*)d_in[7];
    const float* Wv = (const float*)d_in[8];
    const float* bv = (const float*)d_in[9];
    const float* Wo = (const float*)d_in[10];
    const float* bo = (const float*)d_in[11];
    float* out = (float*)d_out;

    cudaFuncSetAttribute(attn_tc, cudaFuncAttributeMaxDynamicSharedMemorySize, ATTN_SMEM);

    fill_prompt<<<(Bb * Pp * Hh * Dd + 255) / 256, 256>>>(prompt);

    dim3 gg(Ee / 128, (Bb * Ss) / 128, 3);
    hgemm_qkv<<<gg, 256>>>(query, key, value, Wq, bq, Wk, bk, Wv, bv);

    attn_tc<<<dim3(Ss / 128, Hh, Bb), 256, ATTN_SMEM>>>();

    hgemm_out<<<dim3(Ee / 128, (Bb * Ss) / 128), 256>>>(Wo, bo, out);
}